// round 4
// baseline (speedup 1.0000x reference)
#include <cuda_runtime.h>
#include <cstdint>

#define B_SZ 64
#define T_SZ 2048
#define I_SZ 256
#define H_SZ 256
#define O_SZ 128
#define M_SZ (B_SZ * T_SZ)   // 131072 rows

// Scratch (device globals: no allocations allowed)
__device__ float g_xp1[(size_t)M_SZ * H_SZ];   // 128 MB
__device__ float g_h1 [(size_t)M_SZ * H_SZ];   // 128 MB
__device__ float g_xp2[(size_t)M_SZ * O_SZ];   //  64 MB

// ---------------------------------------------------------------------------
// Packed fp32x2 FMA (Blackwell)
// ---------------------------------------------------------------------------
union f2u { float2 f; unsigned long long u; };

__device__ __forceinline__ float2 ffma2(float2 a, float2 b, float2 c) {
    f2u A, Bv, C;
    A.f = a; Bv.f = b; C.f = c;
    asm("fma.rn.f32x2 %0, %1, %2, %3;"
        : "=l"(C.u) : "l"(A.u), "l"(Bv.u), "l"(C.u));
    return C.f;
}

// Branch-free fast tanh: MUFU ex2 + fast divide. abs err ~1e-7, no NaN.
__device__ __forceinline__ float fast_tanh(float x) {
    float ax = fabsf(x);
    float e  = __expf(-2.0f * ax);
    float t  = __fdividef(1.0f - e, 1.0f + e);
    return copysignf(t, x);
}

__device__ __forceinline__ uint32_t smem_u32(const void* p) {
    return (uint32_t)__cvta_generic_to_shared(p);
}
__device__ __forceinline__ uint32_t mapa_peer(uint32_t a, unsigned peer) {
    uint32_t r;
    asm("mapa.shared::cluster.u32 %0, %1, %2;" : "=r"(r) : "r"(a), "r"(peer));
    return r;
}
__device__ __forceinline__ void mbar_wait_acq_cluster(uint32_t mbar, uint32_t parity) {
    asm volatile(
        "{\n\t.reg .pred P;\n\t"
        "W_%=:\n\t"
        "mbarrier.try_wait.parity.acquire.cluster.shared::cta.b64 P, [%0], %1;\n\t"
        "@!P bra W_%=;\n\t}"
        :: "r"(mbar), "r"(parity) : "memory");
}

// ---------------------------------------------------------------------------
// SGEMM with fused double-bias: C[M,N] = A[M,K] @ W[N,K]^T + bias_a + bias_b
// ---------------------------------------------------------------------------
__global__ __launch_bounds__(256, 2)
void sgemm_bias_kernel(const float* __restrict__ A,
                       const float* __restrict__ W,
                       const float* __restrict__ bias_a,
                       const float* __restrict__ bias_b,
                       float* __restrict__ C, int K, int N)
{
    constexpr int BM = 128, BN = 128, BK = 16;
    __shared__ float As[BK][BM];
    __shared__ float Bs[BK][BN];

    int tid = threadIdx.x;
    int bm = blockIdx.y * BM;
    int bn = blockIdx.x * BN;
    int tm = tid >> 4;
    int tn = tid & 15;

    float2 acc[8][4];
    #pragma unroll
    for (int i = 0; i < 8; i++)
        #pragma unroll
        for (int j = 0; j < 4; j++) acc[i][j] = make_float2(0.f, 0.f);

    const float* Ab = A + (size_t)bm * K;
    const float* Wb = W + (size_t)bn * K;

    for (int kt = 0; kt < K; kt += BK) {
        #pragma unroll
        for (int it = 0; it < 2; it++) {
            int lid = tid * 2 + it;
            int row = lid >> 2, c4 = lid & 3;
            float4 v = *(const float4*)(Ab + (size_t)row * K + kt + c4 * 4);
            As[c4 * 4 + 0][row] = v.x;
            As[c4 * 4 + 1][row] = v.y;
            As[c4 * 4 + 2][row] = v.z;
            As[c4 * 4 + 3][row] = v.w;
        }
        #pragma unroll
        for (int it = 0; it < 2; it++) {
            int lid = tid * 2 + it;
            int row = lid >> 2, c4 = lid & 3;
            float4 v = *(const float4*)(Wb + (size_t)row * K + kt + c4 * 4);
            Bs[c4 * 4 + 0][row] = v.x;
            Bs[c4 * 4 + 1][row] = v.y;
            Bs[c4 * 4 + 2][row] = v.z;
            Bs[c4 * 4 + 3][row] = v.w;
        }
        __syncthreads();

        #pragma unroll
        for (int kk = 0; kk < BK; kk++) {
            float4 a0 = *(const float4*)&As[kk][tm * 8];
            float4 a1 = *(const float4*)&As[kk][tm * 8 + 4];
            float4 b0 = *(const float4*)&Bs[kk][tn * 8];
            float4 b1 = *(const float4*)&Bs[kk][tn * 8 + 4];
            float av[8] = {a0.x, a0.y, a0.z, a0.w, a1.x, a1.y, a1.z, a1.w};
            float2 bv[4] = {make_float2(b0.x, b0.y), make_float2(b0.z, b0.w),
                            make_float2(b1.x, b1.y), make_float2(b1.z, b1.w)};
            #pragma unroll
            for (int i = 0; i < 8; i++) {
                float2 ai = make_float2(av[i], av[i]);
                #pragma unroll
                for (int j = 0; j < 4; j++)
                    acc[i][j] = ffma2(ai, bv[j], acc[i][j]);
            }
        }
        __syncthreads();
    }

    float2 bb[4];
    #pragma unroll
    for (int j = 0; j < 4; j++) {
        int n = bn + tn * 8 + j * 2;
        bb[j] = make_float2(bias_a[n] + bias_b[n], bias_a[n + 1] + bias_b[n + 1]);
    }
    #pragma unroll
    for (int i = 0; i < 8; i++) {
        int m = bm + tm * 8 + i;
        float* Crow = C + (size_t)m * N + bn + tn * 8;
        #pragma unroll
        for (int j = 0; j < 4; j++) {
            float2 v = make_float2(acc[i][j].x + bb[j].x, acc[i][j].y + bb[j].y);
            *(float2*)(Crow + j * 2) = v;
        }
    }
}

// ---------------------------------------------------------------------------
// Layer-1 scan (cluster-2 per batch), mbarrier peer exchange, warp-partitioned:
//   o = tid&127 (output within CTA half), c = tid>>7 (input chunk, warp-uniform)
// Local-chunk warps start FMAs right after __syncthreads; peer-chunk warps wait
// on an acquire.cluster mbarrier parity (remote arrivals), hiding DSMEM latency.
// ---------------------------------------------------------------------------
__global__ void __cluster_dims__(2, 1, 1) __launch_bounds__(512, 1)
rnn_scan1_kernel(const float* __restrict__ W_hh,
                 const float* __restrict__ xp,
                 float* __restrict__ h1out)
{
    __shared__ float hbuf[2][H_SZ];        // full h, double-buffered
    __shared__ float psum[4][128];
    __shared__ alignas(8) unsigned long long mbar;

    int tid = threadIdx.x;
    int o_l = tid & 127;
    int c   = tid >> 7;                     // 0..3, warp-uniform
    unsigned r;
    asm("mov.u32 %0, %%cluster_ctarank;" : "=r"(r));
    int b = blockIdx.x >> 1;
    int o_global = (int)r * 128 + o_l;
    bool peer_chunk = ((unsigned)(c >> 1) != r);
    bool reducer    = (c == 0);

    // Register-resident weights: W_hh[o_global][c*64 .. c*64+63]
    float2 w2[32];
    {
        const float4* wp = (const float4*)(W_hh + (size_t)o_global * H_SZ + c * 64);
        #pragma unroll
        for (int j = 0; j < 16; j++) {
            float4 v = wp[j];
            w2[2 * j]     = make_float2(v.x, v.y);
            w2[2 * j + 1] = make_float2(v.z, v.w);
        }
    }

    if (tid < 256) hbuf[0][tid] = 0.f;      // h0 = 0
    uint32_t mb = smem_u32(&mbar);
    if (tid == 0)
        asm volatile("mbarrier.init.shared.b64 [%0], %1;" :: "r"(mb), "r"(128) : "memory");

    unsigned peer = r ^ 1u;
    uint32_t rh0 = mapa_peer(smem_u32(&hbuf[0][o_global]), peer);
    uint32_t rh1 = mapa_peer(smem_u32(&hbuf[1][o_global]), peer);
    uint32_t rmb = mapa_peer(mb, peer);

    const float* xpb = xp + (size_t)b * T_SZ * H_SZ + o_global;
    float* hob = h1out + (size_t)b * T_SZ * H_SZ + o_global;

    float pf[4];
    #pragma unroll
    for (int i = 0; i < 4; i++)
        pf[i] = reducer ? __ldg(xpb + (size_t)i * H_SZ) : 0.f;

    __syncthreads();
    // mbar + h0 visible cluster-wide before any remote arrive
    asm volatile("barrier.cluster.arrive.aligned;\n\tbarrier.cluster.wait.aligned;" ::: "memory");

    #pragma unroll 4
    for (int t = 0; t < T_SZ; t++) {
        int p = t & 1;
        // Peer half of h_t: wait for remote stores (phase t-1). Local half is
        // covered by the trailing __syncthreads of the previous step.
        if (t > 0 && peer_chunk)
            mbar_wait_acq_cluster(mb, (uint32_t)((t - 1) & 1));

        const float4* hb = (const float4*)&hbuf[p][c * 64];   // warp-broadcast reads
        float2 a0 = make_float2(0.f, 0.f), a1 = a0, a2 = a0, a3 = a0;
        #pragma unroll
        for (int j = 0; j < 8; j++) {
            float4 h0 = hb[2 * j];
            float4 h1v = hb[2 * j + 1];
            a0 = ffma2(make_float2(h0.x,  h0.y),  w2[4 * j],     a0);
            a1 = ffma2(make_float2(h0.z,  h0.w),  w2[4 * j + 1], a1);
            a2 = ffma2(make_float2(h1v.x, h1v.y), w2[4 * j + 2], a2);
            a3 = ffma2(make_float2(h1v.z, h1v.w), w2[4 * j + 3], a3);
        }
        float s = (a0.x + a1.x) + (a2.x + a3.x) + (a0.y + a1.y) + (a2.y + a3.y);
        if (!reducer) psum[c][o_l] = s;
        __syncthreads();                                   // psums ready

        if (reducer) {
            float xv = pf[t & 3];
            if (t + 4 < T_SZ) pf[t & 3] = __ldg(xpb + (size_t)(t + 4) * H_SZ);
            float tot = s + psum[1][o_l] + psum[2][o_l] + psum[3][o_l] + xv;
            float v = fast_tanh(tot);
            hbuf[p ^ 1][o_global] = v;                     // local copy
            uint32_t ra = p ? rh0 : rh1;                   // peer copy (buffer p^1)
            asm volatile("st.shared::cluster.f32 [%0], %1;" :: "r"(ra), "f"(v) : "memory");
            asm volatile("mbarrier.arrive.release.cluster.shared::cluster.b64 _, [%0];"
                         :: "r"(rmb) : "memory");
            hob[(size_t)t * H_SZ] = v;                     // h1 for layer-2 GEMM
        }
        __syncthreads();                                   // local half of h_{t+1} ready
    }

    // keep SMEM alive until peer's last remote ops land
    asm volatile("barrier.cluster.arrive.aligned;\n\tbarrier.cluster.wait.aligned;" ::: "memory");
}

// ---------------------------------------------------------------------------
// Layer-2 scan: one CTA per batch, same warp-partitioned layout, no cluster.
// ---------------------------------------------------------------------------
__global__ __launch_bounds__(512, 1)
void rnn_scan2_kernel(const float* __restrict__ W_hh,
                      const float* __restrict__ xp,
                      float* __restrict__ out)
{
    __shared__ float hbuf[2][O_SZ];
    __shared__ float psum[4][128];

    int tid = threadIdx.x;
    int o = tid & 127;
    int c = tid >> 7;           // 0..3, 32 inputs each, warp-uniform
    int b = blockIdx.x;
    bool reducer = (c == 0);

    float2 w2[16];
    {
        const float4* wp = (const float4*)(W_hh + (size_t)o * O_SZ + c * 32);
        #pragma unroll
        for (int j = 0; j < 8; j++) {
            float4 v = wp[j];
            w2[2 * j]     = make_float2(v.x, v.y);
            w2[2 * j + 1] = make_float2(v.z, v.w);
        }
    }

    if (tid < 128) hbuf[0][tid] = 0.f;

    const float* xpb = xp + (size_t)b * T_SZ * O_SZ + o;
    float* ob = out + (size_t)b * T_SZ * O_SZ + o;

    float pf[4];
    #pragma unroll
    for (int i = 0; i < 4; i++)
        pf[i] = reducer ? __ldg(xpb + (size_t)i * O_SZ) : 0.f;

    __syncthreads();

    #pragma unroll 4
    for (int t = 0; t < T_SZ; t++) {
        int p = t & 1;
        const float4* hb = (const float4*)&hbuf[p][c * 32];   // warp-broadcast reads
        float2 a0 = make_float2(0.f, 0.f), a1 = a0;
        #pragma unroll
        for (int j = 0; j < 8; j++) {
            float4 hv = hb[j];
            a0 = ffma2(make_float2(hv.x, hv.y), w2[2 * j],     a0);
            a1 = ffma2(make_float2(hv.z, hv.w), w2[2 * j + 1], a1);
        }
        float s = (a0.x + a1.x) + (a0.y + a1.y);
        if (!reducer) psum[c][o] = s;
        __syncthreads();

        if (reducer) {
            float xv = pf[t & 3];
            if (t + 4 < T_SZ) pf[t & 3] = __ldg(xpb + (size_t)(t + 4) * O_SZ);
            float tot = s + psum[1][o] + psum[2][o] + psum[3][o] + xv;
            float v = fast_tanh(tot);
            hbuf[p ^ 1][o] = v;
            ob[(size_t)t * O_SZ] = v;       // final output [B,T,O] flattened
        }
        __syncthreads();
    }
}

// ---------------------------------------------------------------------------
extern "C" void kernel_launch(void* const* d_in, const int* in_sizes, int n_in,
                              void* d_out, int out_size)
{
    const float* x     = (const float*)d_in[0];
    const float* W_ih1 = (const float*)d_in[1];
    const float* W_hh1 = (const float*)d_in[2];
    const float* b_ih1 = (const float*)d_in[3];
    const float* b_hh1 = (const float*)d_in[4];
    const float* W_ih2 = (const float*)d_in[5];
    const float* W_hh2 = (const float*)d_in[6];
    const float* b_ih2 = (const float*)d_in[7];
    const float* b_hh2 = (const float*)d_in[8];
    float* out = (float*)d_out;

    float *xp1, *h1, *xp2;
    cudaGetSymbolAddress((void**)&xp1, g_xp1);
    cudaGetSymbolAddress((void**)&h1,  g_h1);
    cudaGetSymbolAddress((void**)&xp2, g_xp2);

    // Phase 1: xp1 = x @ W_ih1^T + (b_ih1 + b_hh1)   [131072 x 256]
    dim3 g1(H_SZ / 128, M_SZ / 128);
    sgemm_bias_kernel<<<g1, 256>>>(x, W_ih1, b_ih1, b_hh1, xp1, I_SZ, H_SZ);

    // Phase 2: layer-1 recurrent scan (cluster-2 per batch), emits h1
    rnn_scan1_kernel<<<B_SZ * 2, 512>>>(W_hh1, xp1, h1);

    // Phase 3: xp2 = h1 @ W_ih2^T + (b_ih2 + b_hh2)  [131072 x 128]
    dim3 g2(O_SZ / 128, M_SZ / 128);
    sgemm_bias_kernel<<<g2, 256>>>(h1, W_ih2, b_ih2, b_hh2, xp2, H_SZ, O_SZ);

    // Phase 4: layer-2 recurrent scan, writes final output
    rnn_scan2_kernel<<<B_SZ, 512>>>(W_hh2, xp2, out);
}

// round 5
// speedup vs baseline: 1.0963x; 1.0963x over previous
#include <cuda_runtime.h>
#include <cstdint>

#define B_SZ 64
#define T_SZ 2048
#define I_SZ 256
#define H_SZ 256
#define O_SZ 128
#define M_SZ (B_SZ * T_SZ)   // 131072 rows

// Scratch (device globals: no allocations allowed)
__device__ float g_xp1[(size_t)M_SZ * H_SZ];   // 128 MB
__device__ float g_h1 [(size_t)M_SZ * H_SZ];   // 128 MB
__device__ float g_xp2[(size_t)M_SZ * O_SZ];   //  64 MB

// ---------------------------------------------------------------------------
// Packed fp32x2 FMA (Blackwell)
// ---------------------------------------------------------------------------
union f2u { float2 f; unsigned long long u; };

__device__ __forceinline__ float2 ffma2(float2 a, float2 b, float2 c) {
    f2u A, Bv, C;
    A.f = a; Bv.f = b; C.f = c;
    asm("fma.rn.f32x2 %0, %1, %2, %3;"
        : "=l"(C.u) : "l"(A.u), "l"(Bv.u), "l"(C.u));
    return C.f;
}

// Branch-free fast tanh: MUFU ex2 + fast divide. Validated R4 (rel_err 4.4e-7).
__device__ __forceinline__ float fast_tanh(float x) {
    float ax = fabsf(x);
    float e  = __expf(-2.0f * ax);
    float t  = __fdividef(1.0f - e, 1.0f + e);
    return copysignf(t, x);
}

// ---------------------------------------------------------------------------
// SGEMM with fused double-bias: C[M,N] = A[M,K] @ W[N,K]^T + bias_a + bias_b
// ---------------------------------------------------------------------------
__global__ __launch_bounds__(256, 2)
void sgemm_bias_kernel(const float* __restrict__ A,
                       const float* __restrict__ W,
                       const float* __restrict__ bias_a,
                       const float* __restrict__ bias_b,
                       float* __restrict__ C, int K, int N)
{
    constexpr int BM = 128, BN = 128, BK = 16;
    __shared__ float As[BK][BM];
    __shared__ float Bs[BK][BN];

    int tid = threadIdx.x;
    int bm = blockIdx.y * BM;
    int bn = blockIdx.x * BN;
    int tm = tid >> 4;
    int tn = tid & 15;

    float2 acc[8][4];
    #pragma unroll
    for (int i = 0; i < 8; i++)
        #pragma unroll
        for (int j = 0; j < 4; j++) acc[i][j] = make_float2(0.f, 0.f);

    const float* Ab = A + (size_t)bm * K;
    const float* Wb = W + (size_t)bn * K;

    for (int kt = 0; kt < K; kt += BK) {
        #pragma unroll
        for (int it = 0; it < 2; it++) {
            int lid = tid * 2 + it;
            int row = lid >> 2, c4 = lid & 3;
            float4 v = *(const float4*)(Ab + (size_t)row * K + kt + c4 * 4);
            As[c4 * 4 + 0][row] = v.x;
            As[c4 * 4 + 1][row] = v.y;
            As[c4 * 4 + 2][row] = v.z;
            As[c4 * 4 + 3][row] = v.w;
        }
        #pragma unroll
        for (int it = 0; it < 2; it++) {
            int lid = tid * 2 + it;
            int row = lid >> 2, c4 = lid & 3;
            float4 v = *(const float4*)(Wb + (size_t)row * K + kt + c4 * 4);
            Bs[c4 * 4 + 0][row] = v.x;
            Bs[c4 * 4 + 1][row] = v.y;
            Bs[c4 * 4 + 2][row] = v.z;
            Bs[c4 * 4 + 3][row] = v.w;
        }
        __syncthreads();

        #pragma unroll
        for (int kk = 0; kk < BK; kk++) {
            float4 a0 = *(const float4*)&As[kk][tm * 8];
            float4 a1 = *(const float4*)&As[kk][tm * 8 + 4];
            float4 b0 = *(const float4*)&Bs[kk][tn * 8];
            float4 b1 = *(const float4*)&Bs[kk][tn * 8 + 4];
            float av[8] = {a0.x, a0.y, a0.z, a0.w, a1.x, a1.y, a1.z, a1.w};
            float2 bv[4] = {make_float2(b0.x, b0.y), make_float2(b0.z, b0.w),
                            make_float2(b1.x, b1.y), make_float2(b1.z, b1.w)};
            #pragma unroll
            for (int i = 0; i < 8; i++) {
                float2 ai = make_float2(av[i], av[i]);
                #pragma unroll
                for (int j = 0; j < 4; j++)
                    acc[i][j] = ffma2(ai, bv[j], acc[i][j]);
            }
        }
        __syncthreads();
    }

    float2 bb[4];
    #pragma unroll
    for (int j = 0; j < 4; j++) {
        int n = bn + tn * 8 + j * 2;
        bb[j] = make_float2(bias_a[n] + bias_b[n], bias_a[n + 1] + bias_b[n + 1]);
    }
    #pragma unroll
    for (int i = 0; i < 8; i++) {
        int m = bm + tm * 8 + i;
        float* Crow = C + (size_t)m * N + bn + tn * 8;
        #pragma unroll
        for (int j = 0; j < 4; j++) {
            float2 v = make_float2(acc[i][j].x + bb[j].x, acc[i][j].y + bb[j].y);
            *(float2*)(Crow + j * 2) = v;
        }
    }
}

// ---------------------------------------------------------------------------
// Layer-1 scan: cluster of 2 CTAs per batch (round-3 layout), BRANCH-FREE step:
// all 4 lanes of an o-group compute the full sum (butterfly), all compute tanh,
// all store the identical value (write-merge). Split cluster arrive/wait with
// the xp prefetch issued in between.
// ---------------------------------------------------------------------------
__global__ void __cluster_dims__(2, 1, 1) __launch_bounds__(512, 1)
rnn_scan1_kernel(const float* __restrict__ W_hh,
                 const float* __restrict__ xp,
                 float* __restrict__ h1out)
{
    __shared__ float hbuf[2][4 * 68];

    int tid = threadIdx.x;
    int o_local = tid >> 2;     // 0..127
    int c = tid & 3;            // input chunk 0..3 (64 inputs each)
    unsigned r;
    asm("mov.u32 %0, %%cluster_ctarank;" : "=r"(r));
    int b = blockIdx.x >> 1;
    int o_global = (int)r * 128 + o_local;

    // Register-resident weights in rotated order (rotation lives in the SMEM idx)
    float2 w2[32];
    {
        const float4* wp = (const float4*)(W_hh + (size_t)o_global * H_SZ + c * 64);
        #pragma unroll
        for (int j = 0; j < 16; j++) {
            int jj = (j + c * 4) & 15;
            float4 v = wp[jj];
            w2[2 * j]     = make_float2(v.x, v.y);
            w2[2 * j + 1] = make_float2(v.z, v.w);
        }
    }

    if (tid < 256) hbuf[0][(tid >> 6) * 68 + (tid & 63)] = 0.f;   // h0 = 0

    int wpos = (o_global >> 6) * 68 + (o_global & 63);
    uint32_t l0 = (uint32_t)__cvta_generic_to_shared(&hbuf[0][wpos]);
    uint32_t l1 = (uint32_t)__cvta_generic_to_shared(&hbuf[1][wpos]);
    uint32_t rem0, rem1;
    unsigned peer = r ^ 1u;
    asm("mapa.shared::cluster.u32 %0, %1, %2;" : "=r"(rem0) : "r"(l0), "r"(peer));
    asm("mapa.shared::cluster.u32 %0, %1, %2;" : "=r"(rem1) : "r"(l1), "r"(peer));

    const float* xpb = xp + (size_t)b * T_SZ * H_SZ + o_global;
    float* hob = h1out + (size_t)b * T_SZ * H_SZ + o_global;

    // Prefetch pipeline (ALL lanes load the same address -> 1 sector, no branch)
    float pf[4];
    #pragma unroll
    for (int i = 0; i < 4; i++)
        pf[i] = __ldg(xpb + (size_t)i * H_SZ);

    asm volatile("barrier.cluster.arrive.aligned;\n\tbarrier.cluster.wait.aligned;" ::: "memory");

    int p = 0;
    #pragma unroll 4
    for (int t = 0; t < T_SZ; t++) {
        float xv = pf[t & 3];

        const float* hb = &hbuf[p][c * 68];
        float2 a0 = make_float2(0.f, 0.f), a1 = a0, a2 = a0, a3 = a0;
        #pragma unroll
        for (int j = 0; j < 16; j++) {
            int jj = (j + c * 4) & 15;                     // bank-decorrelating rotation
            float4 hv = *(const float4*)(hb + jj * 4);
            float2 h01 = make_float2(hv.x, hv.y);
            float2 h23 = make_float2(hv.z, hv.w);
            if (j & 1) { a2 = ffma2(h01, w2[2 * j], a2); a3 = ffma2(h23, w2[2 * j + 1], a3); }
            else       { a0 = ffma2(h01, w2[2 * j], a0); a1 = ffma2(h23, w2[2 * j + 1], a1); }
        }
        float2 s2 = make_float2(a0.x + a1.x + a2.x + a3.x, a0.y + a1.y + a2.y + a3.y);
        float s = s2.x + s2.y;
        s += __shfl_xor_sync(0xffffffffu, s, 1);           // butterfly: ALL lanes get total
        s += __shfl_xor_sync(0xffffffffu, s, 2);

        float v = fast_tanh(s + xv);                       // all lanes, branch-free
        hbuf[p ^ 1][wpos] = v;                             // 4-way write-merge, local
        uint32_t ra = p ? rem0 : rem1;                     // peer copy (buffer p^1)
        asm volatile("st.shared::cluster.f32 [%0], %1;" :: "r"(ra), "f"(v) : "memory");
        hob[(size_t)t * H_SZ] = v;                         // h1 for layer-2 GEMM (merged)

        // Split barrier: arrive releases the stores; prefetch overlaps the wait.
        asm volatile("barrier.cluster.arrive.aligned;" ::: "memory");
        int tn4 = (t + 4 < T_SZ) ? (t + 4) : (T_SZ - 1);
        pf[t & 3] = __ldg(xpb + (size_t)tn4 * H_SZ);
        asm volatile("barrier.cluster.wait.aligned;" ::: "memory");
        p ^= 1;
    }
}

// ---------------------------------------------------------------------------
// Layer-2 scan: one CTA per batch element, same branch-free pattern.
// ---------------------------------------------------------------------------
__global__ __launch_bounds__(512, 1)
void rnn_scan2_kernel(const float* __restrict__ W_hh,
                      const float* __restrict__ xp,
                      float* __restrict__ out)
{
    __shared__ float obuf[2][4 * 36];

    int tid = threadIdx.x;
    int o = tid >> 2;           // 0..127
    int c = tid & 3;            // 32 inputs each
    int b = blockIdx.x;

    float2 w2[16];
    {
        const float4* wp = (const float4*)(W_hh + (size_t)o * O_SZ + c * 32);
        #pragma unroll
        for (int j = 0; j < 8; j++) {
            int jj = (j + c * 2) & 7;
            float4 v = wp[jj];
            w2[2 * j]     = make_float2(v.x, v.y);
            w2[2 * j + 1] = make_float2(v.z, v.w);
        }
    }

    if (tid < 128) obuf[0][(tid >> 5) * 36 + (tid & 31)] = 0.f;
    int wpos = (o >> 5) * 36 + (o & 31);

    const float* xpb = xp + (size_t)b * T_SZ * O_SZ + o;
    float* ob = out + (size_t)b * T_SZ * O_SZ + o;

    float pf[4];
    #pragma unroll
    for (int i = 0; i < 4; i++)
        pf[i] = __ldg(xpb + (size_t)i * O_SZ);

    __syncthreads();

    int p = 0;
    #pragma unroll 4
    for (int t = 0; t < T_SZ; t++) {
        float xv = pf[t & 3];
        int tn4 = (t + 4 < T_SZ) ? (t + 4) : (T_SZ - 1);
        pf[t & 3] = __ldg(xpb + (size_t)tn4 * O_SZ);

        const float* hb = &obuf[p][c * 36];
        float2 a0 = make_float2(0.f, 0.f), a1 = a0;
        #pragma unroll
        for (int j = 0; j < 8; j++) {
            int jj = (j + c * 2) & 7;
            float4 hv = *(const float4*)(hb + jj * 4);
            a0 = ffma2(make_float2(hv.x, hv.y), w2[2 * j], a0);
            a1 = ffma2(make_float2(hv.z, hv.w), w2[2 * j + 1], a1);
        }
        float s = (a0.x + a1.x) + (a0.y + a1.y);
        s += __shfl_xor_sync(0xffffffffu, s, 1);           // butterfly total
        s += __shfl_xor_sync(0xffffffffu, s, 2);

        float v = fast_tanh(s + xv);                       // all lanes
        obuf[p ^ 1][wpos] = v;                             // write-merge
        ob[(size_t)t * O_SZ] = v;                          // final output (merged)
        __syncthreads();
        p ^= 1;
    }
}

// ---------------------------------------------------------------------------
extern "C" void kernel_launch(void* const* d_in, const int* in_sizes, int n_in,
                              void* d_out, int out_size)
{
    const float* x     = (const float*)d_in[0];
    const float* W_ih1 = (const float*)d_in[1];
    const float* W_hh1 = (const float*)d_in[2];
    const float* b_ih1 = (const float*)d_in[3];
    const float* b_hh1 = (const float*)d_in[4];
    const float* W_ih2 = (const float*)d_in[5];
    const float* W_hh2 = (const float*)d_in[6];
    const float* b_ih2 = (const float*)d_in[7];
    const float* b_hh2 = (const float*)d_in[8];
    float* out = (float*)d_out;

    float *xp1, *h1, *xp2;
    cudaGetSymbolAddress((void**)&xp1, g_xp1);
    cudaGetSymbolAddress((void**)&h1,  g_h1);
    cudaGetSymbolAddress((void**)&xp2, g_xp2);

    // Phase 1: xp1 = x @ W_ih1^T + (b_ih1 + b_hh1)   [131072 x 256]
    dim3 g1(H_SZ / 128, M_SZ / 128);
    sgemm_bias_kernel<<<g1, 256>>>(x, W_ih1, b_ih1, b_hh1, xp1, I_SZ, H_SZ);

    // Phase 2: layer-1 recurrent scan (cluster-2 per batch), emits h1
    rnn_scan1_kernel<<<B_SZ * 2, 512>>>(W_hh1, xp1, h1);

    // Phase 3: xp2 = h1 @ W_ih2^T + (b_ih2 + b_hh2)  [131072 x 128]
    dim3 g2(O_SZ / 128, M_SZ / 128);
    sgemm_bias_kernel<<<g2, 256>>>(h1, W_ih2, b_ih2, b_hh2, xp2, H_SZ, O_SZ);

    // Phase 4: layer-2 recurrent scan, writes final output
    rnn_scan2_kernel<<<B_SZ, 512>>>(W_hh2, xp2, out);
}

// round 6
// speedup vs baseline: 1.1441x; 1.0437x over previous
#include <cuda_runtime.h>
#include <cstdint>

#define B_SZ 64
#define T_SZ 2048
#define I_SZ 256
#define H_SZ 256
#define O_SZ 128
#define M_SZ (B_SZ * T_SZ)   // 131072 rows

// Scratch (device globals: no allocations allowed)
__device__ float g_xp1[(size_t)M_SZ * H_SZ];   // 128 MB
__device__ float g_h1 [(size_t)M_SZ * H_SZ];   // 128 MB
__device__ float g_xp2[(size_t)M_SZ * O_SZ];   //  64 MB

// ---------------------------------------------------------------------------
// Packed fp32x2 FMA (Blackwell)
// ---------------------------------------------------------------------------
union f2u { float2 f; unsigned long long u; };

__device__ __forceinline__ float2 ffma2(float2 a, float2 b, float2 c) {
    f2u A, Bv, C;
    A.f = a; Bv.f = b; C.f = c;
    asm("fma.rn.f32x2 %0, %1, %2, %3;"
        : "=l"(C.u) : "l"(A.u), "l"(Bv.u), "l"(C.u));
    return C.f;
}

// Branch-free fast tanh: MUFU ex2 + fast divide. Validated (rel_err 4.4e-7).
__device__ __forceinline__ float fast_tanh(float x) {
    float ax = fabsf(x);
    float e  = __expf(-2.0f * ax);
    float t  = __fdividef(1.0f - e, 1.0f + e);
    return copysignf(t, x);
}

__device__ __forceinline__ uint32_t smem_u32(const void* p) {
    return (uint32_t)__cvta_generic_to_shared(p);
}
__device__ __forceinline__ uint32_t mapa_peer(uint32_t a, unsigned peer) {
    uint32_t r;
    asm("mapa.shared::cluster.u32 %0, %1, %2;" : "=r"(r) : "r"(a), "r"(peer));
    return r;
}
// Wait for mbarrier phase `parity` with cluster-scope acquire (validated R4).
__device__ __forceinline__ void mbar_wait_acq_cluster(uint32_t mbar, uint32_t parity) {
    asm volatile(
        "{\n\t.reg .pred P;\n\t"
        "W_%=:\n\t"
        "mbarrier.try_wait.parity.acquire.cluster.shared::cta.b64 P, [%0], %1;\n\t"
        "@!P bra W_%=;\n\t}"
        :: "r"(mbar), "r"(parity) : "memory");
}

// ---------------------------------------------------------------------------
// SGEMM with fused double-bias: C[M,N] = A[M,K] @ W[N,K]^T + bias_a + bias_b
// (unchanged from R5 — frozen to isolate the scan1 change)
// ---------------------------------------------------------------------------
__global__ __launch_bounds__(256, 2)
void sgemm_bias_kernel(const float* __restrict__ A,
                       const float* __restrict__ W,
                       const float* __restrict__ bias_a,
                       const float* __restrict__ bias_b,
                       float* __restrict__ C, int K, int N)
{
    constexpr int BM = 128, BN = 128, BK = 16;
    __shared__ float As[BK][BM];
    __shared__ float Bs[BK][BN];

    int tid = threadIdx.x;
    int bm = blockIdx.y * BM;
    int bn = blockIdx.x * BN;
    int tm = tid >> 4;
    int tn = tid & 15;

    float2 acc[8][4];
    #pragma unroll
    for (int i = 0; i < 8; i++)
        #pragma unroll
        for (int j = 0; j < 4; j++) acc[i][j] = make_float2(0.f, 0.f);

    const float* Ab = A + (size_t)bm * K;
    const float* Wb = W + (size_t)bn * K;

    for (int kt = 0; kt < K; kt += BK) {
        #pragma unroll
        for (int it = 0; it < 2; it++) {
            int lid = tid * 2 + it;
            int row = lid >> 2, c4 = lid & 3;
            float4 v = *(const float4*)(Ab + (size_t)row * K + kt + c4 * 4);
            As[c4 * 4 + 0][row] = v.x;
            As[c4 * 4 + 1][row] = v.y;
            As[c4 * 4 + 2][row] = v.z;
            As[c4 * 4 + 3][row] = v.w;
        }
        #pragma unroll
        for (int it = 0; it < 2; it++) {
            int lid = tid * 2 + it;
            int row = lid >> 2, c4 = lid & 3;
            float4 v = *(const float4*)(Wb + (size_t)row * K + kt + c4 * 4);
            Bs[c4 * 4 + 0][row] = v.x;
            Bs[c4 * 4 + 1][row] = v.y;
            Bs[c4 * 4 + 2][row] = v.z;
            Bs[c4 * 4 + 3][row] = v.w;
        }
        __syncthreads();

        #pragma unroll
        for (int kk = 0; kk < BK; kk++) {
            float4 a0 = *(const float4*)&As[kk][tm * 8];
            float4 a1 = *(const float4*)&As[kk][tm * 8 + 4];
            float4 b0 = *(const float4*)&Bs[kk][tn * 8];
            float4 b1 = *(const float4*)&Bs[kk][tn * 8 + 4];
            float av[8] = {a0.x, a0.y, a0.z, a0.w, a1.x, a1.y, a1.z, a1.w};
            float2 bv[4] = {make_float2(b0.x, b0.y), make_float2(b0.z, b0.w),
                            make_float2(b1.x, b1.y), make_float2(b1.z, b1.w)};
            #pragma unroll
            for (int i = 0; i < 8; i++) {
                float2 ai = make_float2(av[i], av[i]);
                #pragma unroll
                for (int j = 0; j < 4; j++)
                    acc[i][j] = ffma2(ai, bv[j], acc[i][j]);
            }
        }
        __syncthreads();
    }

    float2 bb[4];
    #pragma unroll
    for (int j = 0; j < 4; j++) {
        int n = bn + tn * 8 + j * 2;
        bb[j] = make_float2(bias_a[n] + bias_b[n], bias_a[n + 1] + bias_b[n + 1]);
    }
    #pragma unroll
    for (int i = 0; i < 8; i++) {
        int m = bm + tm * 8 + i;
        float* Crow = C + (size_t)m * N + bn + tn * 8;
        #pragma unroll
        for (int j = 0; j < 4; j++) {
            float2 v = make_float2(acc[i][j].x + bb[j].x, acc[i][j].y + bb[j].y);
            *(float2*)(Crow + j * 2) = v;
        }
    }
}

// ---------------------------------------------------------------------------
// Layer-1 scan: cluster-2 per batch. R5 compute skeleton, but the per-step
// cluster barrier (≈490cyc + L1 flush) is replaced by an mbarrier exchange:
//   tanh -> st local + st.shared::cluster peer (data travels early)
//        -> __syncthreads (all reads of old buffer done)
//        -> tid0: mbarrier.arrive.release.cluster on PEER's mbar (count=1)
//   step t starts with try_wait.parity.acquire on phase t-1 (~60cyc wakeup).
// Double-buffer + arrive-after-sync ensures the peer can only overwrite a
// buffer after all local reads of it completed.
// ---------------------------------------------------------------------------
__global__ void __cluster_dims__(2, 1, 1) __launch_bounds__(512, 1)
rnn_scan1_kernel(const float* __restrict__ W_hh,
                 const float* __restrict__ xp,
                 float* __restrict__ h1out)
{
    __shared__ float hbuf[2][4 * 68];
    __shared__ alignas(8) unsigned long long mbar;

    int tid = threadIdx.x;
    int o_local = tid >> 2;     // 0..127
    int c = tid & 3;            // input chunk 0..3 (64 inputs each)
    unsigned r;
    asm("mov.u32 %0, %%cluster_ctarank;" : "=r"(r));
    int b = blockIdx.x >> 1;
    int o_global = (int)r * 128 + o_local;

    // Register-resident weights in rotated order (rotation lives in the SMEM idx)
    float2 w2[32];
    {
        const float4* wp = (const float4*)(W_hh + (size_t)o_global * H_SZ + c * 64);
        #pragma unroll
        for (int j = 0; j < 16; j++) {
            int jj = (j + c * 4) & 15;
            float4 v = wp[jj];
            w2[2 * j]     = make_float2(v.x, v.y);
            w2[2 * j + 1] = make_float2(v.z, v.w);
        }
    }

    if (tid < 256) hbuf[0][(tid >> 6) * 68 + (tid & 63)] = 0.f;   // h0 = 0

    uint32_t mb = smem_u32(&mbar);
    if (tid == 0)
        asm volatile("mbarrier.init.shared.b64 [%0], %1;" :: "r"(mb), "r"(1) : "memory");

    int wpos = (o_global >> 6) * 68 + (o_global & 63);
    uint32_t l0 = smem_u32(&hbuf[0][wpos]);
    uint32_t l1 = smem_u32(&hbuf[1][wpos]);
    unsigned peer = r ^ 1u;
    uint32_t rem0 = mapa_peer(l0, peer);
    uint32_t rem1 = mapa_peer(l1, peer);
    uint32_t rmb  = mapa_peer(mb, peer);

    const float* xpb = xp + (size_t)b * T_SZ * H_SZ + o_global;
    float* hob = h1out + (size_t)b * T_SZ * H_SZ + o_global;

    // Prefetch pipeline (all lanes same address -> 1 sector, branch-free)
    float pf[4];
    #pragma unroll
    for (int i = 0; i < 4; i++)
        pf[i] = __ldg(xpb + (size_t)i * H_SZ);

    // mbar + h0 visible cluster-wide before any remote traffic (once, not per step)
    asm volatile("barrier.cluster.arrive.aligned;\n\tbarrier.cluster.wait.aligned;" ::: "memory");

    int p = 0;
    #pragma unroll 4
    for (int t = 0; t < T_SZ; t++) {
        // Peer half of h_t arrived? (phase t-1). Local half covered by last sync.
        if (t > 0)
            mbar_wait_acq_cluster(mb, (uint32_t)((t - 1) & 1));

        float xv = pf[t & 3];
        int tn4 = (t + 4 < T_SZ) ? (t + 4) : (T_SZ - 1);
        pf[t & 3] = __ldg(xpb + (size_t)tn4 * H_SZ);

        const float* hb = &hbuf[p][c * 68];
        float2 a0 = make_float2(0.f, 0.f), a1 = a0, a2 = a0, a3 = a0;
        #pragma unroll
        for (int j = 0; j < 16; j++) {
            int jj = (j + c * 4) & 15;                     // bank-decorrelating rotation
            float4 hv = *(const float4*)(hb + jj * 4);
            float2 h01 = make_float2(hv.x, hv.y);
            float2 h23 = make_float2(hv.z, hv.w);
            if (j & 1) { a2 = ffma2(h01, w2[2 * j], a2); a3 = ffma2(h23, w2[2 * j + 1], a3); }
            else       { a0 = ffma2(h01, w2[2 * j], a0); a1 = ffma2(h23, w2[2 * j + 1], a1); }
        }
        float2 s2 = make_float2(a0.x + a1.x + a2.x + a3.x, a0.y + a1.y + a2.y + a3.y);
        float s = s2.x + s2.y;
        s += __shfl_xor_sync(0xffffffffu, s, 1);           // butterfly: all lanes get total
        s += __shfl_xor_sync(0xffffffffu, s, 2);

        float v = fast_tanh(s + xv);                       // all lanes, branch-free
        hbuf[p ^ 1][wpos] = v;                             // local copy (write-merge)
        uint32_t ra = p ? rem0 : rem1;                     // peer copy (buffer p^1)
        if (c == 0)                                        // one DSMEM store per o-group
            asm volatile("st.shared::cluster.f32 [%0], %1;" :: "r"(ra), "f"(v) : "memory");
        hob[(size_t)t * H_SZ] = v;                         // h1 for layer-2 GEMM (merged)

        __syncthreads();                                   // all reads of hbuf[p] done
        if (tid == 0)                                      // release: stores -> peer visible
            asm volatile("mbarrier.arrive.release.cluster.shared::cluster.b64 _, [%0];"
                         :: "r"(rmb) : "memory");
        p ^= 1;
    }

    // keep SMEM alive until peer's last remote ops land
    asm volatile("barrier.cluster.arrive.aligned;\n\tbarrier.cluster.wait.aligned;" ::: "memory");
}

// ---------------------------------------------------------------------------
// Layer-2 scan: one CTA per batch element (unchanged from R5).
// ---------------------------------------------------------------------------
__global__ __launch_bounds__(512, 1)
void rnn_scan2_kernel(const float* __restrict__ W_hh,
                      const float* __restrict__ xp,
                      float* __restrict__ out)
{
    __shared__ float obuf[2][4 * 36];

    int tid = threadIdx.x;
    int o = tid >> 2;           // 0..127
    int c = tid & 3;            // 32 inputs each
    int b = blockIdx.x;

    float2 w2[16];
    {
        const float4* wp = (const float4*)(W_hh + (size_t)o * O_SZ + c * 32);
        #pragma unroll
        for (int j = 0; j < 8; j++) {
            int jj = (j + c * 2) & 7;
            float4 v = wp[jj];
            w2[2 * j]     = make_float2(v.x, v.y);
            w2[2 * j + 1] = make_float2(v.z, v.w);
        }
    }

    if (tid < 128) obuf[0][(tid >> 5) * 36 + (tid & 31)] = 0.f;
    int wpos = (o >> 5) * 36 + (o & 31);

    const float* xpb = xp + (size_t)b * T_SZ * O_SZ + o;
    float* ob = out + (size_t)b * T_SZ * O_SZ + o;

    float pf[4];
    #pragma unroll
    for (int i = 0; i < 4; i++)
        pf[i] = __ldg(xpb + (size_t)i * O_SZ);

    __syncthreads();

    int p = 0;
    #pragma unroll 4
    for (int t = 0; t < T_SZ; t++) {
        float xv = pf[t & 3];
        int tn4 = (t + 4 < T_SZ) ? (t + 4) : (T_SZ - 1);
        pf[t & 3] = __ldg(xpb + (size_t)tn4 * O_SZ);

        const float* hb = &obuf[p][c * 36];
        float2 a0 = make_float2(0.f, 0.f), a1 = a0;
        #pragma unroll
        for (int j = 0; j < 8; j++) {
            int jj = (j + c * 2) & 7;
            float4 hv = *(const float4*)(hb + jj * 4);
            a0 = ffma2(make_float2(hv.x, hv.y), w2[2 * j], a0);
            a1 = ffma2(make_float2(hv.z, hv.w), w2[2 * j + 1], a1);
        }
        float s = (a0.x + a1.x) + (a0.y + a1.y);
        s += __shfl_xor_sync(0xffffffffu, s, 1);           // butterfly total
        s += __shfl_xor_sync(0xffffffffu, s, 2);

        float v = fast_tanh(s + xv);                       // all lanes
        obuf[p ^ 1][wpos] = v;                             // write-merge
        ob[(size_t)t * O_SZ] = v;                          // final output (merged)
        __syncthreads();
        p ^= 1;
    }
}

// ---------------------------------------------------------------------------
extern "C" void kernel_launch(void* const* d_in, const int* in_sizes, int n_in,
                              void* d_out, int out_size)
{
    const float* x     = (const float*)d_in[0];
    const float* W_ih1 = (const float*)d_in[1];
    const float* W_hh1 = (const float*)d_in[2];
    const float* b_ih1 = (const float*)d_in[3];
    const float* b_hh1 = (const float*)d_in[4];
    const float* W_ih2 = (const float*)d_in[5];
    const float* W_hh2 = (const float*)d_in[6];
    const float* b_ih2 = (const float*)d_in[7];
    const float* b_hh2 = (const float*)d_in[8];
    float* out = (float*)d_out;

    float *xp1, *h1, *xp2;
    cudaGetSymbolAddress((void**)&xp1, g_xp1);
    cudaGetSymbolAddress((void**)&h1,  g_h1);
    cudaGetSymbolAddress((void**)&xp2, g_xp2);

    // Phase 1: xp1 = x @ W_ih1^T + (b_ih1 + b_hh1)   [131072 x 256]
    dim3 g1(H_SZ / 128, M_SZ / 128);
    sgemm_bias_kernel<<<g1, 256>>>(x, W_ih1, b_ih1, b_hh1, xp1, I_SZ, H_SZ);

    // Phase 2: layer-1 recurrent scan (cluster-2 per batch), emits h1
    rnn_scan1_kernel<<<B_SZ * 2, 512>>>(W_hh1, xp1, h1);

    // Phase 3: xp2 = h1 @ W_ih2^T + (b_ih2 + b_hh2)  [131072 x 128]
    dim3 g2(O_SZ / 128, M_SZ / 128);
    sgemm_bias_kernel<<<g2, 256>>>(h1, W_ih2, b_ih2, b_hh2, xp2, H_SZ, O_SZ);

    // Phase 4: layer-2 recurrent scan, writes final output
    rnn_scan2_kernel<<<B_SZ, 512>>>(W_hh2, xp2, out);
}